// round 14
// baseline (speedup 1.0000x reference)
#include <cuda_runtime.h>
#include <math_constants.h>

// RoiMaxPooling: x (256,56,56,256) f32 NHWC -> adaptive 7x7 max pool (8x8 bins)
// with the reference's transpose/reshape index scramble:
//   out_linear_row = w*(7*B) + h*B + b
//
// R14: THREE independent chains/thread — the untested point on the proven
// lever. Chain sweep: 1 -> 121.0, 2 -> 119.8 (best), 4 -> 123.4 (32 float4
// of load data = 128 regs, impossible; ptxas serialized). 3 chains = 24
// float4 = 96 regs data + accs/addrs ~= 120 regs: fits the winning 128-reg /
// 2-CTA budget with full batching. Tail (12544 bins, 12/block, grid 1046)
// handled branch-free: clamp bin to NBINS-1, duplicate threads re-store the
// identical value (deterministic, keeps load batching undisturbed).

#define B_   256
#define HH   56
#define WW   56
#define CC   256
#define GH   7
#define GW   7

#define NBINS (B_ * GH * GW)   // 12544

__device__ __forceinline__ float4 vmax4(float4 a, float4 b) {
    return make_float4(fmaxf(a.x, b.x), fmaxf(a.y, b.y),
                       fmaxf(a.z, b.z), fmaxf(a.w, b.w));
}

__global__ __launch_bounds__(256, 2)
void roi_maxpool_kernel(const float4* __restrict__ x, float4* __restrict__ out) {
    // Block covers 12 bins: 4 thread-groups of 64 threads, each group owns
    // 3 consecutive bins (three independent chains per thread).
    const int t    = threadIdx.x;
    const int grp  = t >> 6;                          // 0..3
    const int lane = t & 63;                          // channel-group 0..63
    const int bstart = blockIdx.x * 12 + grp * 3;

    const int C4  = CC / 4;        // 64 float4 per pixel
    const int ROW = WW * C4;       // float4 per H-row (3584)

    int base[3], orow[3];
    #pragma unroll
    for (int j = 0; j < 3; j++) {
        int bin = bstart + j;
        bin = bin < NBINS ? bin : (NBINS - 1);   // branch-free tail clamp
        const int b  = bin / (GH * GW);
        const int hw = bin - b * (GH * GW);
        const int h  = hw / GW;
        const int w  = hw - h * GW;
        base[j] = ((b * HH + h * 8) * WW + w * 8) * C4 + lane;
        orow[j] = (w * (GH * B_) + h * B_ + b);
    }

    float4 acc0 = make_float4(-CUDART_INF_F, -CUDART_INF_F,
                              -CUDART_INF_F, -CUDART_INF_F);
    float4 acc1 = acc0, acc2 = acc0;

    #pragma unroll
    for (int i = 0; i < 8; i++) {
        const float4* ra = x + base[0] + i * ROW;
        const float4* rb = x + base[1] + i * ROW;
        const float4* rc = x + base[2] + i * ROW;
        // chain A
        float4 a0 = __ldcs(ra + 0 * C4);
        float4 a1 = __ldcs(ra + 1 * C4);
        float4 a2 = __ldcs(ra + 2 * C4);
        float4 a3 = __ldcs(ra + 3 * C4);
        float4 a4 = __ldcs(ra + 4 * C4);
        float4 a5 = __ldcs(ra + 5 * C4);
        float4 a6 = __ldcs(ra + 6 * C4);
        float4 a7 = __ldcs(ra + 7 * C4);
        // chain B
        float4 b0 = __ldcs(rb + 0 * C4);
        float4 b1 = __ldcs(rb + 1 * C4);
        float4 b2 = __ldcs(rb + 2 * C4);
        float4 b3 = __ldcs(rb + 3 * C4);
        float4 b4 = __ldcs(rb + 4 * C4);
        float4 b5 = __ldcs(rb + 5 * C4);
        float4 b6 = __ldcs(rb + 6 * C4);
        float4 b7 = __ldcs(rb + 7 * C4);
        // chain C
        float4 c0 = __ldcs(rc + 0 * C4);
        float4 c1 = __ldcs(rc + 1 * C4);
        float4 c2 = __ldcs(rc + 2 * C4);
        float4 c3 = __ldcs(rc + 3 * C4);
        float4 c4 = __ldcs(rc + 4 * C4);
        float4 c5 = __ldcs(rc + 5 * C4);
        float4 c6 = __ldcs(rc + 6 * C4);
        float4 c7 = __ldcs(rc + 7 * C4);

        float4 ta = vmax4(vmax4(vmax4(a0, a1), vmax4(a2, a3)),
                          vmax4(vmax4(a4, a5), vmax4(a6, a7)));
        float4 tb = vmax4(vmax4(vmax4(b0, b1), vmax4(b2, b3)),
                          vmax4(vmax4(b4, b5), vmax4(b6, b7)));
        float4 tc = vmax4(vmax4(vmax4(c0, c1), vmax4(c2, c3)),
                          vmax4(vmax4(c4, c5), vmax4(c6, c7)));
        acc0 = vmax4(acc0, ta);
        acc1 = vmax4(acc1, tb);
        acc2 = vmax4(acc2, tc);
    }

    // Scrambled destinations: linear row = w*(GH*B) + h*B + b.
    // Tail duplicates store the identical value to the same address (benign).
    __stcs(out + orow[0] * C4 + lane, acc0);
    __stcs(out + orow[1] * C4 + lane, acc1);
    __stcs(out + orow[2] * C4 + lane, acc2);
}

extern "C" void kernel_launch(void* const* d_in, const int* in_sizes, int n_in,
                              void* d_out, int out_size) {
    const float4* x = (const float4*)d_in[0];
    float4* out = (float4*)d_out;
    const int blocks = (NBINS + 11) / 12;     // 1046 (last block clamps)
    roi_maxpool_kernel<<<blocks, 256>>>(x, out);
}

// round 15
// speedup vs baseline: 1.0263x; 1.0263x over previous
#include <cuda_runtime.h>
#include <math_constants.h>

// RoiMaxPooling: x (256,56,56,256) f32 NHWC -> adaptive 7x7 max pool (8x8 bins)
// with the reference's transpose/reshape index scramble:
//   out_linear_row = w*(7*B) + h*B + b
//
// FINAL = R7 (measured best: 119.8us, 88.5% DRAM, 7.02 TB/s).
// Traffic-minimal HBM stream: 822MB read once + 12.8MB written once.
// Complete design-space map (14 rounds):
//   chains/thread 1/2/3/4     -> 121.0 / 119.8 / 123.6 / 123.4 us
//     (>=3 chains: in-flight float4 data exceeds the 128-reg budget,
//      ptxas splits the load batches -> MLP collapses)
//   CTAs/SM (1-chain) 2/3/4   -> 88.6 / 88.2 / 86.3 % DRAM
//   2 chains x 3 CTAs/SM      -> 125.4 us (80-reg cap splits batches)
//   persistent single-wave    -> 131.0 us (loop broke load pipelining)
//   distant bin pairing       -> 121.2 us (adjacent wins)
//   block 128 vs 256          -> neutral; __ldcs/__stcs -> small win, kept
// All configs steady-state at 85-89% DRAM-active: residual idle is HBM
// physics (refresh/turnaround/launch ramp), not kernel-addressable.
//
// Structure: 64 threads/bin, float4/thread across C=256; each thread owns
// TWO adjacent bins = two fully independent 8-load/vmax chains (16 float4
// in flight = 64 data regs, fits 128-reg / 2-CTA budget), so the scoreboard
// wait at one chain's reduction join is covered by the other chain's
// LDG.128 issue.

#define B_   256
#define HH   56
#define WW   56
#define CC   256
#define GH   7
#define GW   7

__device__ __forceinline__ float4 vmax4(float4 a, float4 b) {
    return make_float4(fmaxf(a.x, b.x), fmaxf(a.y, b.y),
                       fmaxf(a.z, b.z), fmaxf(a.w, b.w));
}

__global__ __launch_bounds__(256, 2)
void roi_maxpool_kernel(const float4* __restrict__ x, float4* __restrict__ out) {
    // Block covers 8 bins: 4 thread-groups of 64 threads, each group owns
    // 2 consecutive bins (two independent chains per thread).
    const int t    = threadIdx.x;
    const int grp  = t >> 6;                          // 0..3
    const int lane = t & 63;                          // channel-group 0..63
    const int bin0 = (blockIdx.x << 3) + (grp << 1);  // even bin
    const int bin1 = bin0 + 1;                        // odd bin

    const int C4  = CC / 4;        // 64 float4 per pixel
    const int ROW = WW * C4;       // float4 per H-row (3584)

    // bin0 coords
    const int b0  = bin0 / (GH * GW);
    const int hw0 = bin0 - b0 * (GH * GW);
    const int h0  = hw0 / GW;
    const int w0  = hw0 - h0 * GW;
    // bin1 coords
    const int b1  = bin1 / (GH * GW);
    const int hw1 = bin1 - b1 * (GH * GW);
    const int h1  = hw1 / GW;
    const int w1  = hw1 - h1 * GW;

    const int base0 = ((b0 * HH + h0 * 8) * WW + w0 * 8) * C4 + lane;
    const int base1 = ((b1 * HH + h1 * 8) * WW + w1 * 8) * C4 + lane;

    float4 accA = make_float4(-CUDART_INF_F, -CUDART_INF_F,
                              -CUDART_INF_F, -CUDART_INF_F);
    float4 accB = accA;

    #pragma unroll
    for (int i = 0; i < 8; i++) {
        const float4* ra = x + base0 + i * ROW;
        const float4* rb = x + base1 + i * ROW;
        // chain A: 8 streaming LDG.128
        float4 a0 = __ldcs(ra + 0 * C4);
        float4 a1 = __ldcs(ra + 1 * C4);
        float4 a2 = __ldcs(ra + 2 * C4);
        float4 a3 = __ldcs(ra + 3 * C4);
        float4 a4 = __ldcs(ra + 4 * C4);
        float4 a5 = __ldcs(ra + 5 * C4);
        float4 a6 = __ldcs(ra + 6 * C4);
        float4 a7 = __ldcs(ra + 7 * C4);
        // chain B: 8 streaming LDG.128 (independent of chain A)
        float4 c0 = __ldcs(rb + 0 * C4);
        float4 c1 = __ldcs(rb + 1 * C4);
        float4 c2 = __ldcs(rb + 2 * C4);
        float4 c3 = __ldcs(rb + 3 * C4);
        float4 c4 = __ldcs(rb + 4 * C4);
        float4 c5 = __ldcs(rb + 5 * C4);
        float4 c6 = __ldcs(rb + 6 * C4);
        float4 c7 = __ldcs(rb + 7 * C4);

        float4 ta = vmax4(vmax4(vmax4(a0, a1), vmax4(a2, a3)),
                          vmax4(vmax4(a4, a5), vmax4(a6, a7)));
        float4 tb = vmax4(vmax4(vmax4(c0, c1), vmax4(c2, c3)),
                          vmax4(vmax4(c4, c5), vmax4(c6, c7)));
        accA = vmax4(accA, ta);
        accB = vmax4(accB, tb);
    }

    // Scrambled destinations: linear row = w*(GH*B) + h*B + b
    const int orow0 = (w0 * (GH * B_) + h0 * B_ + b0);
    const int orow1 = (w1 * (GH * B_) + h1 * B_ + b1);
    __stcs(out + orow0 * C4 + lane, accA);
    __stcs(out + orow1 * C4 + lane, accB);
}

extern "C" void kernel_launch(void* const* d_in, const int* in_sizes, int n_in,
                              void* d_out, int out_size) {
    const float4* x = (const float4*)d_in[0];
    float4* out = (float4*)d_out;
    const int n_bins = B_ * GH * GW;          // 12544
    const int blocks = n_bins / 8;            // 1568
    roi_maxpool_kernel<<<blocks, 256>>>(x, out);
}